// round 11
// baseline (speedup 1.0000x reference)
#include <cuda_runtime.h>
#include <cuda_bf16.h>
#include <math.h>
#include <stdint.h>

// NT-Xent loss, single persistent kernel:
//  phase0: bf16 prep + zero partial-sum arrays
//  phase1: triangular (symmetric) fused HMMA GEMM + streaming base-2 softmax
//          row stats register-carried per band segment; col stats per tile
//  phase2: merge 128 row + 256 col partial slots per row -> per-block sums
//  phase3: block 0 final reduce -> mean loss
// Grid barriers: sense-reversing, self-resetting (graph-replay safe).

#define NTOT   8192
#define NB     64
#define DK     128
#define RS     272
#define NCTA   148
#define SCALE_B2 2.68579530f    // sqrt(log2(e)/0.2)
#define LN2      0.69314718055994531f
#define SKIP_THR 40.0f

__device__ __align__(16) __nv_bfloat16 g_zb[NTOT * DK];
__device__ float g_rowm[128 * NTOT];   // row partials, slot = 2*seg_j0 + wn
__device__ float g_rows[128 * NTOT];
__device__ float g_colm[256 * NTOT];   // col partials, slot = 4*bi + wm
__device__ float g_cols[256 * NTOT];
__device__ float g_t[NTOT];
__device__ float g_bsum[NCTA];
__device__ unsigned g_cnt = 0;
__device__ volatile unsigned g_flag = 0;

// ---------------- helpers ------------------------------------------------
__device__ __forceinline__ float ex2f(float x) {
    float y; asm("ex2.approx.ftz.f32 %0, %1;" : "=f"(y) : "f"(x)); return y;
}
__device__ __forceinline__ uint32_t smem_u32(const void* p) {
    uint32_t a;
    asm("{ .reg .u64 t; cvta.to.shared.u64 t, %1; cvt.u32.u64 %0, t; }"
        : "=r"(a) : "l"(p));
    return a;
}
__device__ __forceinline__ void cp16(uint32_t dst, const void* src) {
    asm volatile("cp.async.cg.shared.global [%0], [%1], 16;"
                 :: "r"(dst), "l"(src) : "memory");
}
__device__ __forceinline__ uint32_t lds32(uint32_t a) {
    uint32_t v; asm volatile("ld.shared.b32 %0, [%1];" : "=r"(v) : "r"(a)); return v;
}
__device__ __forceinline__ void mma16816(float* c, const uint32_t* a,
                                         uint32_t b0, uint32_t b1) {
    asm volatile(
        "mma.sync.aligned.m16n8k16.row.col.f32.bf16.bf16.f32 "
        "{%0,%1,%2,%3}, {%4,%5,%6,%7}, {%8,%9}, {%0,%1,%2,%3};"
        : "+f"(c[0]), "+f"(c[1]), "+f"(c[2]), "+f"(c[3])
        : "r"(a[0]), "r"(a[1]), "r"(a[2]), "r"(a[3]), "r"(b0), "r"(b1));
}
__device__ __forceinline__ void grid_bar() {
    __syncthreads();
    if (threadIdx.x == 0) {
        __threadfence();
        unsigned sense = g_flag;
        if (atomicAdd(&g_cnt, 1u) == NCTA - 1) {
            g_cnt = 0;
            __threadfence();
            g_flag = sense + 1;
        } else {
            while (g_flag == sense) __nanosleep(64);
        }
        __threadfence();
    }
    __syncthreads();
}

// SMEM layout (bytes): A (single), B double buffer
#define SM_A   0
#define SM_B0  34816
#define SM_B1  69632
#define SM_TOT 104448

// ---------------------------------------------------------------------------
__global__ __launch_bounds__(256, 1) void ntxent_all(
    const float* __restrict__ z1, const float* __restrict__ z2,
    float* __restrict__ out) {
    extern __shared__ char smc[];
    const uint32_t smb = smem_u32(smc);
    const int tid  = threadIdx.x;
    const int wid  = tid >> 5;
    const int lane = tid & 31;
    const int q = lane & 3, g = lane >> 2;
    const int wm = wid & 3, wn = wid >> 2;
    const int cta = (int)blockIdx.x;

    // ================= phase 0: prep + zero =================
    {
        const int gt = cta * 256 + tid;
        const int half4 = (NTOT / 2) * DK / 4;
        for (int idx = gt; idx < NTOT * DK / 4; idx += NCTA * 256) {
            float4 v = (idx < half4) ? ((const float4*)z1)[idx]
                                     : ((const float4*)z2)[idx - half4];
            __nv_bfloat162 lo = __floats2bfloat162_rn(v.x * SCALE_B2, v.y * SCALE_B2);
            __nv_bfloat162 hi = __floats2bfloat162_rn(v.z * SCALE_B2, v.w * SCALE_B2);
            __nv_bfloat162* o = (__nv_bfloat162*)&g_zb[idx * 4];
            o[0] = lo; o[1] = hi;
        }
        float4 z4 = make_float4(0.f, 0.f, 0.f, 0.f);
        for (int idx = gt; idx < 128 * NTOT / 4; idx += NCTA * 256)
            ((float4*)g_rows)[idx] = z4;
        for (int idx = gt; idx < 256 * NTOT / 4; idx += NCTA * 256)
            ((float4*)g_cols)[idx] = z4;
    }
    grid_bar();

    // ================= phase 1: triangle sweep =================
    {
        int start = 14 * cta + (cta < 8 ? cta : 8);
        int cnt   = (cta < 8) ? 15 : 14;
        int bi = 0, rem = start;
        while (rem >= NB - bi) { rem -= NB - bi; ++bi; }
        int bj = bi + rem;

        float rm[4], rs[4];
        #pragma unroll
        for (int r = 0; r < 4; ++r) { rm[r] = -INFINITY; rs[r] = 0.f; }
        int curA = -1, segj0 = 0;

        int rloc[4];
        #pragma unroll
        for (int rr = 0; rr < 4; ++rr)
            rloc[rr] = wm * 32 + (rr >> 1) * 16 + (rr & 1) * 8 + g;

        // prologue: B(tile 0) into buf0
        {
            const __nv_bfloat16* zb = &g_zb[bj * 128 * DK];
            #pragma unroll
            for (int k = 0; k < 8; ++k) {
                int u = tid + k * 256;
                int row = u >> 4, c = u & 15;
                cp16(smb + SM_B0 + row * RS + c * 16, zb + row * DK + c * 8);
            }
            asm volatile("cp.async.commit_group;" ::: "memory");
        }

        for (int s = 0; s < cnt; ++s) {
            if (bi != curA) {
                __syncthreads();   // all warps done with previous tile / old A
                if (curA >= 0) {
                    // flush row stats for finished segment
                    #pragma unroll
                    for (int rr = 0; rr < 4; ++rr) {
                        float mx = rm[rr], ss = rs[rr];
                        #pragma unroll
                        for (int off = 1; off <= 2; off <<= 1) {
                            float om = __shfl_xor_sync(0xffffffffu, mx, off);
                            float os = __shfl_xor_sync(0xffffffffu, ss, off);
                            float nm = fmaxf(mx, om);
                            ss = ss * ex2f(mx - nm) + os * ex2f(om - nm);
                            mx = nm;
                        }
                        if (q == 0) {
                            int slot = 2 * segj0 + wn;
                            int a = slot * NTOT + curA * 128 + rloc[rr];
                            g_rowm[a] = mx;
                            g_rows[a] = ss;
                        }
                        rm[rr] = -INFINITY; rs[rr] = 0.f;
                    }
                }
                curA = bi; segj0 = bj;
                const __nv_bfloat16* za = &g_zb[bi * 128 * DK];
                #pragma unroll
                for (int k = 0; k < 8; ++k) {
                    int u = tid + k * 256;
                    int row = u >> 4, c = u & 15;
                    cp16(smb + SM_A + row * RS + c * 16, za + row * DK + c * 8);
                }
                asm volatile("cp.async.commit_group;" ::: "memory");
            }

            asm volatile("cp.async.wait_group 0;" ::: "memory");
            __syncthreads();

            // next tile coords + B prefetch
            int nbi = bi, nbj = bj + 1;
            if (nbj == NB) { ++nbi; nbj = nbi; }
            if (s + 1 < cnt) {
                uint32_t nb = smb + (((s + 1) & 1) ? SM_B1 : SM_B0);
                const __nv_bfloat16* zb = &g_zb[nbj * 128 * DK];
                #pragma unroll
                for (int k = 0; k < 8; ++k) {
                    int u = tid + k * 256;
                    int row = u >> 4, c = u & 15;
                    cp16(nb + row * RS + c * 16, zb + row * DK + c * 8);
                }
                asm volatile("cp.async.commit_group;" ::: "memory");
            }

            const uint32_t sA = smb + SM_A;
            const uint32_t bb = smb + ((s & 1) ? SM_B1 : SM_B0);

            // ---- MMA ----
            float acc[2][8][4];
            #pragma unroll
            for (int mt = 0; mt < 2; ++mt)
                #pragma unroll
                for (int nt = 0; nt < 8; ++nt)
                    #pragma unroll
                    for (int c = 0; c < 4; ++c) acc[mt][nt][c] = 0.f;

            #pragma unroll
            for (int ks = 0; ks < 8; ++ks) {
                uint32_t a[2][4];
                #pragma unroll
                for (int mt = 0; mt < 2; ++mt) {
                    uint32_t ra = sA + (wm * 32 + mt * 16 + g) * RS + ks * 32 + q * 4;
                    a[mt][0] = lds32(ra);
                    a[mt][1] = lds32(ra + 8 * RS);
                    a[mt][2] = lds32(ra + 16);
                    a[mt][3] = lds32(ra + 8 * RS + 16);
                }
                #pragma unroll
                for (int nt = 0; nt < 8; ++nt) {
                    uint32_t rb = bb + (wn * 64 + nt * 8 + g) * RS + ks * 32 + q * 4;
                    uint32_t b0 = lds32(rb);
                    uint32_t b1 = lds32(rb + 16);
                    mma16816(acc[0][nt], a[0], b0, b1);
                    mma16816(acc[1][nt], a[1], b0, b1);
                }
            }

            const bool isDiag = (bi == bj);
            const bool isTgt  = (bj - bi == 32);

            // ---- row-side: update register-carried (m,s) ----
            #pragma unroll
            for (int rr = 0; rr < 4; ++rr) {
                const int mt = rr >> 1, o = (rr & 1) * 2;
                float v[16];
                #pragma unroll
                for (int nt = 0; nt < 8; ++nt) {
                    v[2 * nt]     = acc[mt][nt][o];
                    v[2 * nt + 1] = acc[mt][nt][o + 1];
                }
                if (isDiag || isTgt) {
                    int r_loc = rloc[rr];
                    int lc = r_loc & 63;
                    if ((r_loc >> 6) == wn && ((lc >> 1) & 3) == q) {
                        int vi = (lc >> 3) * 2 + (lc & 1);
                        if (isTgt) {
                            float vd = v[vi];
                            g_t[bi * 128 + r_loc] = vd;
                            g_t[bj * 128 + r_loc] = vd;
                        } else {
                            v[vi] = -INFINITY;
                        }
                    }
                }
                float m0 = fmaxf(v[0], v[1]),   m1 = fmaxf(v[2], v[3]);
                float m2 = fmaxf(v[4], v[5]),   m3 = fmaxf(v[6], v[7]);
                float m4 = fmaxf(v[8], v[9]),   m5 = fmaxf(v[10], v[11]);
                float m6 = fmaxf(v[12], v[13]), m7 = fmaxf(v[14], v[15]);
                float gA = fmaxf(m0, m1), gB = fmaxf(m2, m3);
                float gC = fmaxf(m4, m5), gD = fmaxf(m6, m7);
                float mx = fmaxf(fmaxf(gA, gB), fmaxf(gC, gD));
                if (mx > rm[rr] - SKIP_THR) {
                    float mn = fmaxf(rm[rr], mx);
                    float ss = rs[rr] * ex2f(rm[rr] - mn);
                    if (gA > mn - SKIP_THR)
                        ss += ex2f(v[0]-mn) + ex2f(v[1]-mn) + ex2f(v[2]-mn) + ex2f(v[3]-mn);
                    if (gB > mn - SKIP_THR)
                        ss += ex2f(v[4]-mn) + ex2f(v[5]-mn) + ex2f(v[6]-mn) + ex2f(v[7]-mn);
                    if (gC > mn - SKIP_THR)
                        ss += ex2f(v[8]-mn) + ex2f(v[9]-mn) + ex2f(v[10]-mn) + ex2f(v[11]-mn);
                    if (gD > mn - SKIP_THR)
                        ss += ex2f(v[12]-mn) + ex2f(v[13]-mn) + ex2f(v[14]-mn) + ex2f(v[15]-mn);
                    rs[rr] = ss;
                    rm[rr] = mn;
                }
            }

            // ---- col-side: per-tile partials, direct per-warp global write ----
            if (!isDiag) {
                int slot = 4 * bi + wm;
                int base = slot * NTOT + bj * 128;
                #pragma unroll
                for (int nt = 0; nt < 8; ++nt) {
                    #pragma unroll
                    for (int par = 0; par < 2; ++par) {
                        float x0 = acc[0][nt][par], x1 = acc[0][nt][2 + par];
                        float x2 = acc[1][nt][par], x3 = acc[1][nt][2 + par];
                        float myMax = fmaxf(fmaxf(x0, x1), fmaxf(x2, x3));
                        float cm = myMax;
                        #pragma unroll
                        for (int off = 4; off <= 16; off <<= 1)
                            cm = fmaxf(cm, __shfl_xor_sync(0xffffffffu, cm, off));
                        float cs = 0.f;
                        if (myMax > cm - SKIP_THR)
                            cs = ex2f(x0-cm) + ex2f(x1-cm) + ex2f(x2-cm) + ex2f(x3-cm);
                        #pragma unroll
                        for (int off = 4; off <= 16; off <<= 1)
                            cs += __shfl_xor_sync(0xffffffffu, cs, off);
                        if (g == 0) {
                            int c_loc = wn * 64 + nt * 8 + 2 * q + par;
                            g_colm[base + c_loc] = cm;
                            g_cols[base + c_loc] = cs;
                        }
                    }
                }
            }

            bi = nbi; bj = nbj;
        }

        // final segment flush
        if (curA >= 0) {
            #pragma unroll
            for (int rr = 0; rr < 4; ++rr) {
                float mx = rm[rr], ss = rs[rr];
                #pragma unroll
                for (int off = 1; off <= 2; off <<= 1) {
                    float om = __shfl_xor_sync(0xffffffffu, mx, off);
                    float os = __shfl_xor_sync(0xffffffffu, ss, off);
                    float nm = fmaxf(mx, om);
                    ss = ss * ex2f(mx - nm) + os * ex2f(om - nm);
                    mx = nm;
                }
                if (q == 0) {
                    int slot = 2 * segj0 + wn;
                    int a = slot * NTOT + curA * 128 + rloc[rr];
                    g_rowm[a] = mx;
                    g_rows[a] = ss;
                }
            }
        }
    }
    grid_bar();

    // ================= phase 2: combine -> block sums =================
    {
        int gid = cta * 256 + tid;
        int row = gid >> 2, qq = gid & 3;
        float loss = 0.f;
        if (row < NTOT) {
            float m = -INFINITY, ssum = 0.f;
            #pragma unroll 4
            for (int p = qq * 32; p < qq * 32 + 32; ++p) {
                float sp = g_rows[p * NTOT + row];
                if (sp > 0.f) {
                    float mp = g_rowm[p * NTOT + row];
                    float nm = fmaxf(m, mp);
                    ssum = ssum * ex2f(m - nm) + sp * ex2f(mp - nm);
                    m = nm;
                }
            }
            #pragma unroll 4
            for (int p = qq * 64; p < qq * 64 + 64; ++p) {
                float sp = g_cols[p * NTOT + row];
                if (sp > 0.f) {
                    float mp = g_colm[p * NTOT + row];
                    float nm = fmaxf(m, mp);
                    ssum = ssum * ex2f(m - nm) + sp * ex2f(mp - nm);
                    m = nm;
                }
            }
            #pragma unroll
            for (int off = 1; off <= 2; off <<= 1) {
                float om = __shfl_xor_sync(0xffffffffu, m, off);
                float os = __shfl_xor_sync(0xffffffffu, ssum, off);
                float nm = fmaxf(m, om);
                float sa = (ssum > 0.f) ? ssum * ex2f(m - nm) : 0.f;
                float sb = (os   > 0.f) ? os   * ex2f(om - nm) : 0.f;
                ssum = sa + sb;
                m = nm;
            }
            if (qq == 0) loss = m + __log2f(ssum) - g_t[row];
        }
        float* red = (float*)smc;
        red[tid] = loss;
        __syncthreads();
        for (int st = 128; st > 0; st >>= 1) {
            if (tid < st) red[tid] += red[tid + st];
            __syncthreads();
        }
        if (tid == 0) g_bsum[cta] = red[0];
    }
    grid_bar();

    // ================= phase 3: final reduce =================
    if (cta == 0) {
        float* red = (float*)smc;
        red[tid] = (tid < NCTA) ? g_bsum[tid] : 0.f;
        __syncthreads();
        for (int st = 128; st > 0; st >>= 1) {
            if (tid < st) red[tid] += red[tid + st];
            __syncthreads();
        }
        if (tid == 0) out[0] = red[0] * (LN2 / (float)NTOT);
    }
}

// ---------------------------------------------------------------------------
extern "C" void kernel_launch(void* const* d_in, const int* in_sizes, int n_in,
                              void* d_out, int out_size) {
    const float* z1 = (const float*)d_in[0];
    const float* z2 = (const float*)d_in[1];
    float* out = (float*)d_out;

    cudaFuncSetAttribute(ntxent_all,
                         cudaFuncAttributeMaxDynamicSharedMemorySize, SM_TOT);
    ntxent_all<<<NCTA, 256, SM_TOT>>>(z1, z2, out);
}

// round 12
// speedup vs baseline: 1.1868x; 1.1868x over previous
#include <cuda_runtime.h>
#include <cuda_bf16.h>
#include <math.h>
#include <stdint.h>

// NT-Xent loss: fused bf16 mma.sync GEMM + streaming base-2 softmax.
// R12 = R5 (32x64 warp tiles, 256 thr, full GEMM) with ldmatrix fragment loads.

#define NTOT   8192
#define BHALF  4096
#define DK     128
#define TM     128
#define TNJ    128              // cols per j-tile
#define NJT    32               // j-tiles per CTA (4096/128)
#define RS     272              // smem row stride bytes (128 bf16 + 8 pad)
#define SCALE_B2 2.68579530f    // sqrt(log2(e)/0.2)
#define LN2      0.69314718055994531f
#define SKIP_THR 40.0f

__device__ __align__(16) __nv_bfloat16 g_zb[NTOT * DK];
__device__ float g_m[4 * NTOT];   // partials: p = half*2 + wn
__device__ float g_s[4 * NTOT];
__device__ float g_t[4 * NTOT];

// ---------------------------------------------------------------------------
__global__ void prep_kernel(const float* __restrict__ z1,
                            const float* __restrict__ z2) {
    int idx = blockIdx.x * blockDim.x + threadIdx.x;      // float4 index
    const int half4 = BHALF * DK / 4;
    float4 v = (idx < half4) ? ((const float4*)z1)[idx]
                             : ((const float4*)z2)[idx - half4];
    __nv_bfloat162 lo = __floats2bfloat162_rn(v.x * SCALE_B2, v.y * SCALE_B2);
    __nv_bfloat162 hi = __floats2bfloat162_rn(v.z * SCALE_B2, v.w * SCALE_B2);
    __nv_bfloat162* o = (__nv_bfloat162*)&g_zb[idx * 4];
    o[0] = lo; o[1] = hi;
}

// ---------------------------------------------------------------------------
__device__ __forceinline__ float ex2f(float x) {
    float y; asm("ex2.approx.ftz.f32 %0, %1;" : "=f"(y) : "f"(x)); return y;
}
__device__ __forceinline__ uint32_t smem_u32(const void* p) {
    uint32_t a;
    asm("{ .reg .u64 t; cvta.to.shared.u64 t, %1; cvt.u32.u64 %0, t; }"
        : "=r"(a) : "l"(p));
    return a;
}
__device__ __forceinline__ void cp16(uint32_t dst, const void* src) {
    asm volatile("cp.async.cg.shared.global [%0], [%1], 16;"
                 :: "r"(dst), "l"(src) : "memory");
}
__device__ __forceinline__ void ldsm4(uint32_t* r, uint32_t a) {
    asm volatile("ldmatrix.sync.aligned.m8n8.x4.shared.b16 {%0,%1,%2,%3}, [%4];"
                 : "=r"(r[0]), "=r"(r[1]), "=r"(r[2]), "=r"(r[3]) : "r"(a));
}
__device__ __forceinline__ void mma16816(float* c, const uint32_t* a,
                                         uint32_t b0, uint32_t b1) {
    asm volatile(
        "mma.sync.aligned.m16n8k16.row.col.f32.bf16.bf16.f32 "
        "{%0,%1,%2,%3}, {%4,%5,%6,%7}, {%8,%9}, {%0,%1,%2,%3};"
        : "+f"(c[0]), "+f"(c[1]), "+f"(c[2]), "+f"(c[3])
        : "r"(a[0]), "r"(a[1]), "r"(a[2]), "r"(a[3]), "r"(b0), "r"(b1));
}

// ---------------------------------------------------------------------------
// 128 CTAs x 256 threads. CTA b: rows (b>>1)*128, col half (b&1)*4096.
// smem: A tile [128][RS], B double buffer 2x[128][RS].
// Warp w: wm=w&3 row block (32 rows), wn=w>>2 col block (64 cols).
// ---------------------------------------------------------------------------
__global__ __launch_bounds__(256, 1) void ntxent_kernel() {
    extern __shared__ char smc[];
    const uint32_t smb = smem_u32(smc);
    const int tid  = threadIdx.x;
    const int wid  = tid >> 5;
    const int lane = tid & 31;
    const int q = lane & 3, g = lane >> 2;
    const int wm = wid & 3, wn = wid >> 2;
    const int i0 = (int)(blockIdx.x >> 1) * TM;
    const int half = blockIdx.x & 1;
    const int jh = half * BHALF;

    const uint32_t sA  = smb;
    const uint32_t sB0 = smb + 128 * RS;
    const uint32_t sB1 = sB0 + 128 * RS;

    // ldmatrix lane-address components (validated in R6)
    const int a_row8 = (lane & 7) + ((lane >> 3) & 1) * 8;   // row within 16
    const int a_kb   = (lane >> 4) * 16;                     // k-half byte offset
    const int b_nrow = (lane & 7) + (lane >> 4) * 8;         // n within 16
    const int b_kb   = ((lane >> 3) & 1) * 16;

    // Prologue: A tile + B tile 0. 2048 16B chunks each / 256 thr.
    #pragma unroll
    for (int k = 0; k < 8; ++k) {
        int u = tid + k * 256;
        int row = u >> 4, c = u & 15;
        cp16(sA + row * RS + c * 16, &g_zb[(i0 + row) * DK + c * 8]);
    }
    #pragma unroll
    for (int k = 0; k < 8; ++k) {
        int u = tid + k * 256;
        int row = u >> 4, c = u & 15;
        cp16(sB0 + row * RS + c * 16, &g_zb[(jh + row) * DK + c * 8]);
    }
    asm volatile("cp.async.commit_group;" ::: "memory");

    float rm[4], rs[4], tv[4];
    #pragma unroll
    for (int r = 0; r < 4; ++r) { rm[r] = -INFINITY; rs[r] = 0.f; tv[r] = -INFINITY; }

    int rowid[4];
    #pragma unroll
    for (int rr = 0; rr < 4; ++rr)
        rowid[rr] = i0 + wm * 32 + (rr >> 1) * 16 + (rr & 1) * 8 + g;

    const uint32_t aAddrBase = sA + (wm * 32 + a_row8) * RS + a_kb;

    for (int jt = 0; jt < NJT; ++jt) {
        asm volatile("cp.async.wait_group 0;" ::: "memory");
        __syncthreads();

        if (jt + 1 < NJT) {
            uint32_t nb = ((jt + 1) & 1) ? sB1 : sB0;
            int jr0 = jh + (jt + 1) * TNJ;
            #pragma unroll
            for (int k = 0; k < 8; ++k) {
                int u = tid + k * 256;
                int row = u >> 4, c = u & 15;
                cp16(nb + row * RS + c * 16, &g_zb[(jr0 + row) * DK + c * 8]);
            }
            asm volatile("cp.async.commit_group;" ::: "memory");
        }

        const uint32_t bb = (jt & 1) ? sB1 : sB0;
        const uint32_t bAddrBase = bb + (wn * 64 + b_nrow) * RS + b_kb;

        float acc[2][8][4];
        #pragma unroll
        for (int mt = 0; mt < 2; ++mt)
            #pragma unroll
            for (int nt = 0; nt < 8; ++nt)
                #pragma unroll
                for (int c = 0; c < 4; ++c) acc[mt][nt][c] = 0.f;

        #pragma unroll
        for (int ks = 0; ks < 8; ++ks) {
            uint32_t a[2][4], b[4][4];   // b[p] serves nt = 2p (r0,r1), 2p+1 (r2,r3)
            ldsm4(a[0], aAddrBase + ks * 32);
            ldsm4(a[1], aAddrBase + 16 * RS + ks * 32);
            #pragma unroll
            for (int p = 0; p < 4; ++p)
                ldsm4(b[p], bAddrBase + p * 16 * RS + ks * 32);
            #pragma unroll
            for (int p = 0; p < 4; ++p) {
                mma16816(acc[0][2 * p],     a[0], b[p][0], b[p][1]);
                mma16816(acc[1][2 * p],     a[1], b[p][0], b[p][1]);
                mma16816(acc[0][2 * p + 1], a[0], b[p][2], b[p][3]);
                mma16816(acc[1][2 * p + 1], a[1], b[p][2], b[p][3]);
            }
        }

        // Fused epilogue (verbatim R5): online (m,s); rare diag/target fixup.
        int jbase = jh + jt * TNJ + wn * 64;
        #pragma unroll
        for (int rr = 0; rr < 4; ++rr) {
            const int mt = rr >> 1, o = (rr & 1) * 2;
            const int r = rowid[rr];
            float v[16];
            #pragma unroll
            for (int nt = 0; nt < 8; ++nt) {
                v[2 * nt]     = acc[mt][nt][o];
                v[2 * nt + 1] = acc[mt][nt][o + 1];
            }
            int tcol = (r + BHALF) & (NTOT - 1);
            if ((unsigned)(r - jbase) < 64u || (unsigned)(tcol - jbase) < 64u) {
                #pragma unroll
                for (int e = 0; e < 16; ++e) {
                    int j = jbase + (e >> 1) * 8 + 2 * q + (e & 1);
                    if (j == tcol) tv[rr] = v[e];
                    if (j == r)    v[e] = -INFINITY;   // diag mask
                }
            }
            float m0 = fmaxf(v[0], v[1]),   m1 = fmaxf(v[2], v[3]);
            float m2 = fmaxf(v[4], v[5]),   m3 = fmaxf(v[6], v[7]);
            float m4 = fmaxf(v[8], v[9]),   m5 = fmaxf(v[10], v[11]);
            float m6 = fmaxf(v[12], v[13]), m7 = fmaxf(v[14], v[15]);
            float mx = fmaxf(fmaxf(fmaxf(m0, m1), fmaxf(m2, m3)),
                             fmaxf(fmaxf(m4, m5), fmaxf(m6, m7)));
            if (mx > rm[rr] - SKIP_THR) {
                float mn = fmaxf(rm[rr], mx);
                float a0 = rs[rr] * ex2f(rm[rr] - mn);
                float a1 = 0.f, a2 = 0.f, a3 = 0.f;
                #pragma unroll
                for (int e = 0; e < 16; e += 4) {
                    a0 += ex2f(v[e]     - mn);
                    a1 += ex2f(v[e + 1] - mn);
                    a2 += ex2f(v[e + 2] - mn);
                    a3 += ex2f(v[e + 3] - mn);
                }
                rs[rr] = (a0 + a1) + (a2 + a3);
                rm[rr] = mn;
            }
        }
    }

    // Quad reduction (lanes q=0..3 share the same rows, disjoint cols).
    #pragma unroll
    for (int off = 1; off <= 2; off <<= 1) {
        #pragma unroll
        for (int rr = 0; rr < 4; ++rr) {
            float m2 = __shfl_xor_sync(0xffffffffu, rm[rr], off);
            float s2 = __shfl_xor_sync(0xffffffffu, rs[rr], off);
            float t2 = __shfl_xor_sync(0xffffffffu, tv[rr], off);
            float nm = fmaxf(rm[rr], m2);
            rs[rr] = rs[rr] * ex2f(rm[rr] - nm) + s2 * ex2f(m2 - nm);
            rm[rr] = nm;
            tv[rr] = fmaxf(tv[rr], t2);
        }
    }
    if (q == 0) {
        int p = half * 2 + wn;
        #pragma unroll
        for (int rr = 0; rr < 4; ++rr) {
            int idx = p * NTOT + rowid[rr];
            g_m[idx] = rm[rr];
            g_s[idx] = rs[rr];
            g_t[idx] = tv[rr];
        }
    }
}

// ---------------------------------------------------------------------------
__global__ void combine_kernel(float* __restrict__ out) {
    __shared__ float red[256];
    int tid = threadIdx.x;
    float acc = 0.0f;
    for (int i = tid; i < NTOT; i += 256) {
        float m = -INFINITY, t = -INFINITY;
        #pragma unroll
        for (int p = 0; p < 4; ++p) {
            m = fmaxf(m, g_m[p * NTOT + i]);
            t = fmaxf(t, g_t[p * NTOT + i]);
        }
        float s = 0.0f;
        #pragma unroll
        for (int p = 0; p < 4; ++p)
            s += g_s[p * NTOT + i] * exp2f(g_m[p * NTOT + i] - m);
        acc += (m + log2f(s) - t);
    }
    red[tid] = acc;
    __syncthreads();
    for (int st = 128; st > 0; st >>= 1) {
        if (tid < st) red[tid] += red[tid + st];
        __syncthreads();
    }
    if (tid == 0) out[0] = red[0] * (LN2 / (float)NTOT);
}

// ---------------------------------------------------------------------------
extern "C" void kernel_launch(void* const* d_in, const int* in_sizes, int n_in,
                              void* d_out, int out_size) {
    const float* z1 = (const float*)d_in[0];
    const float* z2 = (const float*)d_in[1];
    float* out = (float*)d_out;

    const int smem_bytes = 3 * 128 * RS;   // 104448 B
    cudaFuncSetAttribute(ntxent_kernel,
                         cudaFuncAttributeMaxDynamicSharedMemorySize, smem_bytes);

    prep_kernel<<<(NTOT * DK / 4) / 256, 256>>>(z1, z2);
    ntxent_kernel<<<NTOT / TM * 2, 256, smem_bytes>>>();
    combine_kernel<<<1, 256>>>(out);
}

// round 13
// speedup vs baseline: 1.3507x; 1.1381x over previous
#include <cuda_runtime.h>
#include <cuda_bf16.h>
#include <math.h>
#include <stdint.h>

// NT-Xent loss, single persistent kernel.
// phase0: bf16 prep (scale by sqrt(log2e/T))
// phase1: fused bf16 mma.sync GEMM + streaming base-2 softmax
//         (512 thr/CTA, 4x4 warp grid, 32x64 warp tiles = R12 inner loop)
// phase2: combine 8 partials per row -> per-CTA sums
// phase3: CTA0 final mean.

#define NTOT   8192
#define BHALF  4096
#define DK     128
#define TM     128
#define TNJ    256              // cols per j-tile
#define NJT    16               // j-tiles per CTA (4096/256)
#define RS     272              // smem row stride bytes (128 bf16 + 8 pad)
#define NCTA   128
#define SCALE_B2 2.68579530f    // sqrt(log2(e)/0.2)
#define LN2      0.69314718055994531f
#define SKIP_THR 40.0f

__device__ __align__(16) __nv_bfloat16 g_zb[NTOT * DK];
__device__ float g_m[8 * NTOT];   // partials: p = half*4 + wn
__device__ float g_s[8 * NTOT];
__device__ float g_t[8 * NTOT];
__device__ float g_bsum[NCTA];
__device__ unsigned g_cnt = 0;
__device__ volatile unsigned g_flag = 0;

// ---------------- helpers ------------------------------------------------
__device__ __forceinline__ float ex2f(float x) {
    float y; asm("ex2.approx.ftz.f32 %0, %1;" : "=f"(y) : "f"(x)); return y;
}
__device__ __forceinline__ uint32_t smem_u32(const void* p) {
    uint32_t a;
    asm("{ .reg .u64 t; cvta.to.shared.u64 t, %1; cvt.u32.u64 %0, t; }"
        : "=r"(a) : "l"(p));
    return a;
}
__device__ __forceinline__ void cp16(uint32_t dst, const void* src) {
    asm volatile("cp.async.cg.shared.global [%0], [%1], 16;"
                 :: "r"(dst), "l"(src) : "memory");
}
__device__ __forceinline__ void ldsm4(uint32_t* r, uint32_t a) {
    asm volatile("ldmatrix.sync.aligned.m8n8.x4.shared.b16 {%0,%1,%2,%3}, [%4];"
                 : "=r"(r[0]), "=r"(r[1]), "=r"(r[2]), "=r"(r[3]) : "r"(a));
}
__device__ __forceinline__ void mma16816(float* c, const uint32_t* a,
                                         uint32_t b0, uint32_t b1) {
    asm volatile(
        "mma.sync.aligned.m16n8k16.row.col.f32.bf16.bf16.f32 "
        "{%0,%1,%2,%3}, {%4,%5,%6,%7}, {%8,%9}, {%0,%1,%2,%3};"
        : "+f"(c[0]), "+f"(c[1]), "+f"(c[2]), "+f"(c[3])
        : "r"(a[0]), "r"(a[1]), "r"(a[2]), "r"(a[3]), "r"(b0), "r"(b1));
}
__device__ __forceinline__ void grid_bar() {
    __syncthreads();
    if (threadIdx.x == 0) {
        __threadfence();
        unsigned sense = g_flag;
        if (atomicAdd(&g_cnt, 1u) == NCTA - 1) {
            g_cnt = 0;
            __threadfence();
            g_flag = sense + 1;
        } else {
            while (g_flag == sense) __nanosleep(64);
        }
        __threadfence();
    }
    __syncthreads();
}

// SMEM layout (bytes)
#define SM_A   0
#define SM_B0  34816                       // A: 128*272
#define SM_B1  (SM_B0 + 256 * RS)          // 104448
#define SM_TOT (SM_B1 + 256 * RS)          // 174080

// ---------------------------------------------------------------------------
__global__ __launch_bounds__(512, 1) void ntxent_all(
    const float* __restrict__ z1, const float* __restrict__ z2,
    float* __restrict__ out) {
    extern __shared__ char smc[];
    const uint32_t smb = smem_u32(smc);
    const int tid  = threadIdx.x;
    const int wid  = tid >> 5;
    const int lane = tid & 31;
    const int q = lane & 3, g = lane >> 2;
    const int wm = wid & 3, wn = wid >> 2;           // 4 x 4 warp grid
    const int cta = (int)blockIdx.x;

    // ================= phase 0: prep =================
    {
        const int half4 = BHALF * DK / 4;
        for (int idx = cta * 512 + tid; idx < NTOT * DK / 4; idx += NCTA * 512) {
            float4 v = (idx < half4) ? ((const float4*)z1)[idx]
                                     : ((const float4*)z2)[idx - half4];
            __nv_bfloat162 lo = __floats2bfloat162_rn(v.x * SCALE_B2, v.y * SCALE_B2);
            __nv_bfloat162 hi = __floats2bfloat162_rn(v.z * SCALE_B2, v.w * SCALE_B2);
            __nv_bfloat162* o = (__nv_bfloat162*)&g_zb[idx * 4];
            o[0] = lo; o[1] = hi;
        }
    }
    grid_bar();

    // ================= phase 1: GEMM + streaming softmax =================
    {
        const int i0 = (cta >> 1) * TM;
        const int half = cta & 1;
        const int jh = half * BHALF;

        const uint32_t sA  = smb + SM_A;
        const uint32_t sB0 = smb + SM_B0;
        const uint32_t sB1 = smb + SM_B1;

        const int a_row8 = (lane & 7) + ((lane >> 3) & 1) * 8;
        const int a_kb   = (lane >> 4) * 16;
        const int b_nrow = (lane & 7) + (lane >> 4) * 8;
        const int b_kb   = ((lane >> 3) & 1) * 16;

        // Prologue: A tile (2048 chunks) + B tile 0 (4096 chunks), 512 thr.
        #pragma unroll
        for (int k = 0; k < 4; ++k) {
            int u = tid + k * 512;
            int row = u >> 4, c = u & 15;
            cp16(sA + row * RS + c * 16, &g_zb[(i0 + row) * DK + c * 8]);
        }
        #pragma unroll
        for (int k = 0; k < 8; ++k) {
            int u = tid + k * 512;
            int row = u >> 4, c = u & 15;
            cp16(sB0 + row * RS + c * 16, &g_zb[(jh + row) * DK + c * 8]);
        }
        asm volatile("cp.async.commit_group;" ::: "memory");

        float rm[4], rs[4], tv[4];
        #pragma unroll
        for (int r = 0; r < 4; ++r) { rm[r] = -INFINITY; rs[r] = 0.f; tv[r] = -INFINITY; }

        int rowid[4];
        #pragma unroll
        for (int rr = 0; rr < 4; ++rr)
            rowid[rr] = i0 + wm * 32 + (rr >> 1) * 16 + (rr & 1) * 8 + g;

        const uint32_t aAddrBase = sA + (wm * 32 + a_row8) * RS + a_kb;

        for (int jt = 0; jt < NJT; ++jt) {
            asm volatile("cp.async.wait_group 0;" ::: "memory");
            __syncthreads();

            if (jt + 1 < NJT) {
                uint32_t nb = ((jt + 1) & 1) ? sB1 : sB0;
                int jr0 = jh + (jt + 1) * TNJ;
                #pragma unroll
                for (int k = 0; k < 8; ++k) {
                    int u = tid + k * 512;
                    int row = u >> 4, c = u & 15;
                    cp16(nb + row * RS + c * 16, &g_zb[(jr0 + row) * DK + c * 8]);
                }
                asm volatile("cp.async.commit_group;" ::: "memory");
            }

            const uint32_t bb = (jt & 1) ? sB1 : sB0;
            const uint32_t bAddrBase = bb + (wn * 64 + b_nrow) * RS + b_kb;

            float acc[2][8][4];
            #pragma unroll
            for (int mt = 0; mt < 2; ++mt)
                #pragma unroll
                for (int nt = 0; nt < 8; ++nt)
                    #pragma unroll
                    for (int c = 0; c < 4; ++c) acc[mt][nt][c] = 0.f;

            #pragma unroll
            for (int ks = 0; ks < 8; ++ks) {
                uint32_t a[2][4], b[4][4];
                ldsm4(a[0], aAddrBase + ks * 32);
                ldsm4(a[1], aAddrBase + 16 * RS + ks * 32);
                #pragma unroll
                for (int p = 0; p < 4; ++p)
                    ldsm4(b[p], bAddrBase + p * 16 * RS + ks * 32);
                #pragma unroll
                for (int p = 0; p < 4; ++p) {
                    mma16816(acc[0][2 * p],     a[0], b[p][0], b[p][1]);
                    mma16816(acc[1][2 * p],     a[1], b[p][0], b[p][1]);
                    mma16816(acc[0][2 * p + 1], a[0], b[p][2], b[p][3]);
                    mma16816(acc[1][2 * p + 1], a[1], b[p][2], b[p][3]);
                }
            }

            // Fused epilogue: online (m, s); rare diag/target fixup.
            int jbase = jh + jt * TNJ + wn * 64;
            #pragma unroll
            for (int rr = 0; rr < 4; ++rr) {
                const int mt = rr >> 1, o = (rr & 1) * 2;
                const int r = rowid[rr];
                float v[16];
                #pragma unroll
                for (int nt = 0; nt < 8; ++nt) {
                    v[2 * nt]     = acc[mt][nt][o];
                    v[2 * nt + 1] = acc[mt][nt][o + 1];
                }
                int tcol = (r + BHALF) & (NTOT - 1);
                if ((unsigned)(r - jbase) < 64u || (unsigned)(tcol - jbase) < 64u) {
                    #pragma unroll
                    for (int e = 0; e < 16; ++e) {
                        int j = jbase + (e >> 1) * 8 + 2 * q + (e & 1);
                        if (j == tcol) tv[rr] = v[e];
                        if (j == r)    v[e] = -INFINITY;   // diag mask
                    }
                }
                float m0 = fmaxf(v[0], v[1]),   m1 = fmaxf(v[2], v[3]);
                float m2 = fmaxf(v[4], v[5]),   m3 = fmaxf(v[6], v[7]);
                float m4 = fmaxf(v[8], v[9]),   m5 = fmaxf(v[10], v[11]);
                float m6 = fmaxf(v[12], v[13]), m7 = fmaxf(v[14], v[15]);
                float mx = fmaxf(fmaxf(fmaxf(m0, m1), fmaxf(m2, m3)),
                                 fmaxf(fmaxf(m4, m5), fmaxf(m6, m7)));
                if (mx > rm[rr] - SKIP_THR) {
                    float mn = fmaxf(rm[rr], mx);
                    float a0 = rs[rr] * ex2f(rm[rr] - mn);
                    float a1 = 0.f, a2 = 0.f, a3 = 0.f;
                    #pragma unroll
                    for (int e = 0; e < 16; e += 4) {
                        a0 += ex2f(v[e]     - mn);
                        a1 += ex2f(v[e + 1] - mn);
                        a2 += ex2f(v[e + 2] - mn);
                        a3 += ex2f(v[e + 3] - mn);
                    }
                    rs[rr] = (a0 + a1) + (a2 + a3);
                    rm[rr] = mn;
                }
            }
        }

        // Quad reduction (lanes q=0..3 share rows, disjoint cols).
        #pragma unroll
        for (int off = 1; off <= 2; off <<= 1) {
            #pragma unroll
            for (int rr = 0; rr < 4; ++rr) {
                float m2 = __shfl_xor_sync(0xffffffffu, rm[rr], off);
                float s2 = __shfl_xor_sync(0xffffffffu, rs[rr], off);
                float t2 = __shfl_xor_sync(0xffffffffu, tv[rr], off);
                float nm = fmaxf(rm[rr], m2);
                rs[rr] = rs[rr] * ex2f(rm[rr] - nm) + s2 * ex2f(m2 - nm);
                rm[rr] = nm;
                tv[rr] = fmaxf(tv[rr], t2);
            }
        }
        if (q == 0) {
            int p = half * 4 + wn;
            #pragma unroll
            for (int rr = 0; rr < 4; ++rr) {
                int idx = p * NTOT + rowid[rr];
                g_m[idx] = rm[rr];
                g_s[idx] = rs[rr];
                g_t[idx] = tv[rr];
            }
        }
    }
    grid_bar();

    // ================= phase 2: combine -> per-CTA sums =================
    {
        int row = cta * 512 + tid;   // rows live in CTAs 0..15
        float loss = 0.f;
        if (row < NTOT) {
            float m = -INFINITY, t = -INFINITY;
            #pragma unroll
            for (int p = 0; p < 8; ++p) {
                m = fmaxf(m, g_m[p * NTOT + row]);
                t = fmaxf(t, g_t[p * NTOT + row]);
            }
            float s = 0.f;
            #pragma unroll
            for (int p = 0; p < 8; ++p)
                s += g_s[p * NTOT + row] * ex2f(g_m[p * NTOT + row] - m);
            loss = m + __log2f(s) - t;
        }
        float* red = (float*)smc;
        red[tid] = loss;
        __syncthreads();
        for (int st = 256; st > 0; st >>= 1) {
            if (tid < st) red[tid] += red[tid + st];
            __syncthreads();
        }
        if (tid == 0) g_bsum[cta] = red[0];
    }
    grid_bar();

    // ================= phase 3: final reduce =================
    if (cta == 0) {
        float* red = (float*)smc;
        red[tid] = (tid < NCTA) ? g_bsum[tid] : 0.f;
        __syncthreads();
        for (int st = 64; st > 0; st >>= 1) {
            if (tid < st) red[tid] += red[tid + st];
            __syncthreads();
        }
        if (tid == 0) out[0] = red[0] * (LN2 / (float)NTOT);
    }
}

// ---------------------------------------------------------------------------
extern "C" void kernel_launch(void* const* d_in, const int* in_sizes, int n_in,
                              void* d_out, int out_size) {
    const float* z1 = (const float*)d_in[0];
    const float* z2 = (const float*)d_in[1];
    float* out = (float*)d_out;

    cudaFuncSetAttribute(ntxent_all,
                         cudaFuncAttributeMaxDynamicSharedMemorySize, SM_TOT);
    ntxent_all<<<NCTA, 512, SM_TOT>>>(z1, z2, out);
}